// round 4
// baseline (speedup 1.0000x reference)
#include <cuda_runtime.h>
#include <math.h>

#define B_IMG 8
#define N_PROP 1000
#define C_CLS 91
#define CM1 90
#define NCAND 90000      // N_PROP * CM1
#define K_TOP 2048
#define DET 36
#define D_FEAT 1024
#define BBOX_CLIP 4.135166556742356f

// ---------------- scratch (static device globals; zero-init at load) ---------
__device__ unsigned long long g_list[B_IMG][NCAND];   // packed (score_bits<<32 | ~flat_idx)
__device__ int                g_M[B_IMG];             // valid counts; reset by fused_kernel

// ---------------- helpers ----------------------------------------------------
__device__ __forceinline__ float4 decode_clip(const float* __restrict__ reg,
                                              const float* __restrict__ props,
                                              int b, unsigned int flat,
                                              float wImg, float hImg) {
    int n = (int)(flat / CM1);
    int c = (int)(flat % CM1) + 1;            // skip background
    const float* p = props + ((size_t)b * N_PROP + n) * 4;
    float p0 = p[0], p1 = p[1], p2 = p[2], p3 = p[3];
    float wp = __fsub_rn(p2, p0);
    float hp = __fsub_rn(p3, p1);
    float cx = __fadd_rn(p0, __fmul_rn(0.5f, wp));
    float cy = __fadd_rn(p1, __fmul_rn(0.5f, hp));
    const float* r = reg + ((size_t)b * N_PROP + n) * (C_CLS * 4) + c * 4;
    float dx = __fdiv_rn(r[0], 10.0f);
    float dy = __fdiv_rn(r[1], 10.0f);
    float dw = fminf(__fdiv_rn(r[2], 5.0f), BBOX_CLIP);
    float dh = fminf(__fdiv_rn(r[3], 5.0f), BBOX_CLIP);
    float pcx = __fadd_rn(__fmul_rn(dx, wp), cx);
    float pcy = __fadd_rn(__fmul_rn(dy, hp), cy);
    float pw  = __fmul_rn(expf(dw), wp);
    float ph  = __fmul_rn(expf(dh), hp);
    float x1 = __fsub_rn(pcx, __fmul_rn(0.5f, pw));
    float y1 = __fsub_rn(pcy, __fmul_rn(0.5f, ph));
    float x2 = __fadd_rn(pcx, __fmul_rn(0.5f, pw));
    float y2 = __fadd_rn(pcy, __fmul_rn(0.5f, ph));
    x1 = fminf(fmaxf(x1, 0.0f), wImg);
    y1 = fminf(fmaxf(y1, 0.0f), hImg);
    x2 = fminf(fmaxf(x2, 0.0f), wImg);
    y2 = fminf(fmaxf(y2, 0.0f), hImg);
    return make_float4(x1, y1, x2, y2);
}

// ---------------- kernel 1: softmax + filter + compact (warp per proposal) ---
__global__ __launch_bounds__(256)
void score_kernel(const float* __restrict__ logits,
                  const float* __restrict__ reg,
                  const float* __restrict__ props,
                  const int*   __restrict__ img_hw) {
    int warp = (blockIdx.x * blockDim.x + threadIdx.x) >> 5;   // 0..7999
    int lane = threadIdx.x & 31;
    int b = warp / N_PROP;
    int n = warp % N_PROP;

    const float* lrow = logits + (size_t)warp * C_CLS;
    float l0 = lrow[lane];
    float l1 = (lane + 32 < C_CLS) ? lrow[lane + 32] : -INFINITY;
    float l2 = (lane + 64 < C_CLS) ? lrow[lane + 64] : -INFINITY;

    // max (exact, order-free)
    float m = fmaxf(fmaxf(l0, l2), l1);
    #pragma unroll
    for (int s = 16; s > 0; s >>= 1)
        m = fmaxf(m, __shfl_xor_sync(0xffffffffu, m, s));
    m = __shfl_sync(0xffffffffu, m, 0);

    float e0 = expf(__fsub_rn(l0, m));
    float e1 = expf(__fsub_rn(l1, m));   // expf(-inf)=+0 matches zero-pad
    float e2 = expf(__fsub_rn(l2, m));

    float v = __fadd_rn(__fadd_rn(e0, e2), e1);
    #pragma unroll
    for (int s = 16; s > 0; s >>= 1)
        v = __fadd_rn(v, __shfl_xor_sync(0xffffffffu, v, s));
    float ssum = __shfl_sync(0xffffffffu, v, 0);

    float hImg = (float)img_hw[b * 2 + 0];
    float wImg = (float)img_hw[b * 2 + 1];

    float ecls[3] = {e0, e1, e2};
    #pragma unroll
    for (int k = 0; k < 3; ++k) {
        int c = lane + 32 * k;
        if (c >= 1 && c < C_CLS) {
            float score = __fdiv_rn(ecls[k], ssum);
            if (score > 0.2f) {
                unsigned int flat = (unsigned int)(n * CM1 + (c - 1));
                float4 box = decode_clip(reg, props, b, flat, wImg, hImg);
                if (__fsub_rn(box.z, box.x) >= 0.01f && __fsub_rn(box.w, box.y) >= 0.01f) {
                    int pos = atomicAdd(&g_M[b], 1);
                    unsigned long long key =
                        ((unsigned long long)__float_as_uint(score) << 32) |
                        (unsigned long long)(unsigned int)(~flat);
                    g_list[b][pos] = key;
                }
            }
        }
    }
}

// ---------------- bitonic sort (descending), hybrid warp/block sync ----------
// For stride j < 16 (and previous stride < 32), compare-swap pairs stay inside
// one warp's contiguous 32-element blocks -> __syncwarp suffices.
__device__ void bitonic_desc(unsigned long long* buf, int n) {
    for (int k = 2; k <= n; k <<= 1) {
        for (int j = k >> 1; j > 0; j >>= 1) {
            if (j >= 16) __syncthreads(); else __syncwarp();
            for (int i = threadIdx.x; i < n; i += blockDim.x) {
                int ixj = i ^ j;
                if (ixj > i) {
                    unsigned long long a = buf[i], c = buf[ixj];
                    bool descSeg = ((i & k) == 0);
                    if (descSeg ? (a < c) : (a > c)) { buf[i] = c; buf[ixj] = a; }
                }
            }
        }
    }
    __syncthreads();
}

// ---------------- kernel 2: fused top-K sort + NMS + feature gather ----------
// one block per image, 1024 threads
__global__ __launch_bounds__(1024)
void fused_kernel(const float* __restrict__ reg,
                  const float* __restrict__ props,
                  const int*   __restrict__ img_hw,
                  const float* __restrict__ feats,
                  float* __restrict__ out) {
    __shared__ unsigned long long buf[4096];       // 32KB; aliased as sbox after sort
    __shared__ unsigned int  sidx[K_TOP];          // 8KB: flat candidate indices
    __shared__ unsigned char skeep[K_TOP];         // 2KB
    __shared__ int skept[DET];
    __shared__ unsigned int s_warpb[32];
    __shared__ int s_next;

    int b = blockIdx.x;
    int tid = threadIdx.x;
    int M = g_M[b];

    // ---- sort: runtime-size bitonic + tournament for M > 4096 ----
    int loaded = min(M, 4096);
    int n = 64;
    while (n < loaded) n <<= 1;
    for (int i = tid; i < n; i += blockDim.x)
        buf[i] = (i < loaded) ? g_list[b][i] : 0ull;
    bitonic_desc(buf, n);

    int consumed = loaded;
    while (consumed < M) {       // keep top 2048, refill bottom half
        int take = min(M - consumed, 2048);
        for (int s = tid; s < 2048; s += blockDim.x)
            buf[2048 + s] = (s < take) ? g_list[b][consumed + s] : 0ull;
        consumed += take;
        bitonic_desc(buf, 4096);
    }

    int K = min(M, K_TOP);

    // ---- extract flat indices (buf keys die after this) ----
    for (int s = tid; s < K; s += blockDim.x)
        sidx[s] = ~(unsigned int)(buf[s] & 0xffffffffull);
    __syncthreads();

    // ---- decode boxes into smem (aliases buf) ----
    float4* sbox = (float4*)buf;
    float hImg = (float)img_hw[b * 2 + 0];
    float wImg = (float)img_hw[b * 2 + 1];
    for (int s = tid; s < K; s += blockDim.x) {
        sbox[s] = decode_clip(reg, props, b, sidx[s], wImg, hImg);
        skeep[s] = 1;
    }
    __syncthreads();

    // ---- greedy NMS: ballot-based next-unsuppressed skip, early exit @DET ----
    int kc = 0;
    int base = 0;
    while (base < K && kc < DET) {
        // find first slot >= base with skeep==1 within a 1024 window
        int slot = base + tid;
        bool f = (slot < K) && (skeep[slot] != 0);
        unsigned int wb = __ballot_sync(0xffffffffu, f);
        if ((tid & 31) == 0) s_warpb[tid >> 5] = wb;
        __syncthreads();
        if (tid < 32) {
            unsigned int w = s_warpb[tid];
            unsigned int has = __ballot_sync(0xffffffffu, w != 0);
            if (tid == 0) {
                int nxt = -1;
                if (has) {
                    int fw = __ffs(has) - 1;
                    int fb = __ffs(s_warpb[fw]) - 1;
                    nxt = base + fw * 32 + fb;
                }
                s_next = nxt;
            }
        }
        __syncthreads();
        int i = s_next;
        if (i < 0) { base += 1024; continue; }   // whole window suppressed

        // keep candidate i; suppress overlapping j > i
        if (tid == 0) skept[kc] = i;
        float4 a = sbox[i];
        float areaA = __fmul_rn(__fsub_rn(a.z, a.x), __fsub_rn(a.w, a.y));
        for (int j = i + 1 + tid; j < K; j += blockDim.x) {
            if (skeep[j]) {
                float4 c = sbox[j];
                float ltx = fmaxf(a.x, c.x), lty = fmaxf(a.y, c.y);
                float rbx = fminf(a.z, c.z), rby = fminf(a.w, c.w);
                float w = fmaxf(__fsub_rn(rbx, ltx), 0.0f);
                float h = fmaxf(__fsub_rn(rby, lty), 0.0f);
                float inter = __fmul_rn(w, h);
                if (inter > 0.0f) {
                    float areaC = __fmul_rn(__fsub_rn(c.z, c.x), __fsub_rn(c.w, c.y));
                    float uni = __fsub_rn(__fadd_rn(areaA, areaC), inter);
                    if (__fdiv_rn(inter, uni) > 0.5f) skeep[j] = 0;
                }
            }
        }
        kc++;
        base = i + 1;
        __syncthreads();   // skeep writes + skept visible before next round
    }
    __syncthreads();

    // ---- feature gather: 36 rows x 256 float4, all threads ----
    for (int idx = tid; idx < DET * (D_FEAT / 4); idx += blockDim.x) {
        int t = idx >> 8;            // detection slot
        int q = idx & 255;           // float4 within row
        float4* dst = (float4*)(out + ((size_t)b * DET + t) * D_FEAT);
        if (t < kc) {
            int pn = (int)(sidx[skept[t]] / CM1);
            const float4* src = (const float4*)(feats + ((size_t)b * N_PROP + pn) * D_FEAT);
            dst[q] = src[q];
        } else {
            dst[q] = make_float4(0.f, 0.f, 0.f, 0.f);
        }
    }

    // ---- self-reset for next graph replay ----
    if (tid == 0) g_M[b] = 0;
}

// ---------------- launch ------------------------------------------------------
extern "C" void kernel_launch(void* const* d_in, const int* in_sizes, int n_in,
                              void* d_out, int out_size) {
    const float* logits = (const float*)d_in[0];   // [8,1000,91]
    const float* reg    = (const float*)d_in[1];   // [8,1000,364]
    const float* props  = (const float*)d_in[2];   // [8,1000,4]
    const float* feats  = (const float*)d_in[3];   // [8,1000,1024]
    const int*   imghw  = (const int*)d_in[4];     // [8,2]
    float* out = (float*)d_out;                    // [8,36,1024]

    score_kernel<<<B_IMG * N_PROP / 8, 256>>>(logits, reg, props, imghw);
    fused_kernel<<<B_IMG, 1024>>>(reg, props, imghw, feats, out);
}

// round 5
// speedup vs baseline: 1.3604x; 1.3604x over previous
#include <cuda_runtime.h>
#include <math.h>

#define B_IMG 8
#define N_PROP 1000
#define C_CLS 91
#define CM1 90
#define NCAND 90000      // N_PROP * CM1
#define K_TOP 2048
#define DET 36
#define D_FEAT 1024
#define BBOX_CLIP 4.135166556742356f

typedef unsigned long long u64;

// ---------------- scratch (static device globals; zero-init at load) ---------
__device__ u64 g_list[B_IMG][NCAND];   // packed (score_bits<<32 | ~flat_idx)
__device__ int g_M[B_IMG];             // valid counts; reset by fused_kernel

// ---------------- helpers ----------------------------------------------------
__device__ __forceinline__ float4 decode_clip(const float* __restrict__ reg,
                                              const float* __restrict__ props,
                                              int b, unsigned int flat,
                                              float wImg, float hImg) {
    int n = (int)(flat / CM1);
    int c = (int)(flat % CM1) + 1;            // skip background
    const float* p = props + ((size_t)b * N_PROP + n) * 4;
    float p0 = p[0], p1 = p[1], p2 = p[2], p3 = p[3];
    float wp = __fsub_rn(p2, p0);
    float hp = __fsub_rn(p3, p1);
    float cx = __fadd_rn(p0, __fmul_rn(0.5f, wp));
    float cy = __fadd_rn(p1, __fmul_rn(0.5f, hp));
    const float* r = reg + ((size_t)b * N_PROP + n) * (C_CLS * 4) + c * 4;
    float dx = __fdiv_rn(r[0], 10.0f);
    float dy = __fdiv_rn(r[1], 10.0f);
    float dw = fminf(__fdiv_rn(r[2], 5.0f), BBOX_CLIP);
    float dh = fminf(__fdiv_rn(r[3], 5.0f), BBOX_CLIP);
    float pcx = __fadd_rn(__fmul_rn(dx, wp), cx);
    float pcy = __fadd_rn(__fmul_rn(dy, hp), cy);
    float pw  = __fmul_rn(expf(dw), wp);
    float ph  = __fmul_rn(expf(dh), hp);
    float x1 = __fsub_rn(pcx, __fmul_rn(0.5f, pw));
    float y1 = __fsub_rn(pcy, __fmul_rn(0.5f, ph));
    float x2 = __fadd_rn(pcx, __fmul_rn(0.5f, pw));
    float y2 = __fadd_rn(pcy, __fmul_rn(0.5f, ph));
    x1 = fminf(fmaxf(x1, 0.0f), wImg);
    y1 = fminf(fmaxf(y1, 0.0f), hImg);
    x2 = fminf(fmaxf(x2, 0.0f), wImg);
    y2 = fminf(fmaxf(y2, 0.0f), hImg);
    return make_float4(x1, y1, x2, y2);
}

// ---------------- kernel 1: softmax + filter + compact (warp per proposal) ---
__global__ __launch_bounds__(256)
void score_kernel(const float* __restrict__ logits,
                  const float* __restrict__ reg,
                  const float* __restrict__ props,
                  const int*   __restrict__ img_hw) {
    int warp = (blockIdx.x * blockDim.x + threadIdx.x) >> 5;   // 0..7999
    int lane = threadIdx.x & 31;
    int b = warp / N_PROP;
    int n = warp % N_PROP;

    const float* lrow = logits + (size_t)warp * C_CLS;
    float l0 = lrow[lane];
    float l1 = (lane + 32 < C_CLS) ? lrow[lane + 32] : -INFINITY;
    float l2 = (lane + 64 < C_CLS) ? lrow[lane + 64] : -INFINITY;

    float m = fmaxf(fmaxf(l0, l2), l1);
    #pragma unroll
    for (int s = 16; s > 0; s >>= 1)
        m = fmaxf(m, __shfl_xor_sync(0xffffffffu, m, s));
    m = __shfl_sync(0xffffffffu, m, 0);

    float e0 = expf(__fsub_rn(l0, m));
    float e1 = expf(__fsub_rn(l1, m));   // expf(-inf)=+0 matches zero-pad
    float e2 = expf(__fsub_rn(l2, m));

    float v = __fadd_rn(__fadd_rn(e0, e2), e1);
    #pragma unroll
    for (int s = 16; s > 0; s >>= 1)
        v = __fadd_rn(v, __shfl_xor_sync(0xffffffffu, v, s));
    float ssum = __shfl_sync(0xffffffffu, v, 0);

    float hImg = (float)img_hw[b * 2 + 0];
    float wImg = (float)img_hw[b * 2 + 1];

    float ecls[3] = {e0, e1, e2};
    #pragma unroll
    for (int k = 0; k < 3; ++k) {
        int c = lane + 32 * k;
        if (c >= 1 && c < C_CLS) {
            float score = __fdiv_rn(ecls[k], ssum);
            if (score > 0.2f) {
                unsigned int flat = (unsigned int)(n * CM1 + (c - 1));
                float4 box = decode_clip(reg, props, b, flat, wImg, hImg);
                if (__fsub_rn(box.z, box.x) >= 0.01f && __fsub_rn(box.w, box.y) >= 0.01f) {
                    int pos = atomicAdd(&g_M[b], 1);
                    u64 key = ((u64)__float_as_uint(score) << 32) |
                              (u64)(unsigned int)(~flat);
                    g_list[b][pos] = key;
                }
            }
        }
    }
}

// ---------------- register/shuffle bitonic primitives ------------------------
__device__ __forceinline__ u64 cex(u64 v, u64 p, bool takeMax) {
    return takeMax ? (v > p ? v : p) : (v < p ? v : p);
}

// Full descending bitonic sort of 2048 elements; thread holds v0@i0, v1@i1.
// i0 = (tid>>5)*64 + lane, i1 = i0 + 32. Comparator network identical to the
// classic formulation: partner i^j, descending segment when (i & k) == 0.
__device__ __forceinline__ void sort2048(u64& v0, u64& v1, u64* buf,
                                         int i0, int i1) {
    for (int k = 2; k <= 2048; k <<= 1) {
        // smem steps: j >= 64
        for (int j = k >> 1; j >= 64; j >>= 1) {
            buf[i0] = v0; buf[i1] = v1;
            __syncthreads();
            u64 p0 = buf[i0 ^ j], p1 = buf[i1 ^ j];
            __syncthreads();
            v0 = cex(v0, p0, ((i0 & j) == 0) == ((i0 & k) == 0));
            v1 = cex(v1, p1, ((i1 & j) == 0) == ((i1 & k) == 0));
        }
        // j = 32: partner is the other register of the same thread
        if (k > 32) {
            bool desc = ((i0 & k) == 0);
            u64 a = v0, c = v1;
            v0 = desc ? (a > c ? a : c) : (a < c ? a : c);
            v1 = desc ? (a > c ? c : a) : (a < c ? c : a);
        }
        // j <= 16: warp shuffles
        int jst = (k >> 1) < 16 ? (k >> 1) : 16;
        for (int j = jst; j >= 1; j >>= 1) {
            u64 p0 = __shfl_xor_sync(0xffffffffu, v0, j);
            u64 p1 = __shfl_xor_sync(0xffffffffu, v1, j);
            v0 = cex(v0, p0, ((i0 & j) == 0) == ((i0 & k) == 0));
            v1 = cex(v1, p1, ((i1 & j) == 0) == ((i1 & k) == 0));
        }
    }
}

// ---------------- kernel 2: fused top-K sort + NMS + feature gather ----------
// one block per image, 1024 threads
__global__ __launch_bounds__(1024)
void fused_kernel(const float* __restrict__ reg,
                  const float* __restrict__ props,
                  const int*   __restrict__ img_hw,
                  const float* __restrict__ feats,
                  float* __restrict__ out) {
    __shared__ u64 buf[4096];                      // 32KB; sort scratch, then sbox
    __shared__ unsigned int  sidx[K_TOP];          // 8KB
    __shared__ unsigned char skeep[K_TOP];         // 2KB
    __shared__ int skept[DET];

    int b = blockIdx.x;
    int tid = threadIdx.x;
    int i0 = ((tid >> 5) << 6) + (tid & 31);       // warp-block element 0
    int i1 = i0 + 32;
    int M = g_M[b];

    // ---- sort first chunk (pad with 0 keys; real keys are all > 0) ----
    int loaded = min(M, K_TOP);
    u64 v0 = (i0 < loaded) ? g_list[b][i0] : 0ull;
    u64 v1 = (i1 < loaded) ? g_list[b][i1] : 0ull;
    sort2048(v0, v1, buf, i0, i1);

    // ---- exact top-2048 merge of further chunks (rare path) ----
    int consumed = loaded;
    while (consumed < M) {
        int take = min(M - consumed, K_TOP);
        u64 u0 = (i0 < take) ? g_list[b][consumed + i0] : 0ull;
        u64 u1 = (i1 < take) ? g_list[b][consumed + i1] : 0ull;
        consumed += take;
        sort2048(u0, u1, buf, i0, i1);
        // stride 2048 of 4096-merge: v[i] = max(v[i], u[2047-i])
        buf[i0] = u0; buf[i1] = u1;
        __syncthreads();
        u64 p0 = buf[2047 - i0], p1 = buf[2047 - i1];
        __syncthreads();
        v0 = v0 > p0 ? v0 : p0;
        v1 = v1 > p1 ? v1 : p1;
        // descending merge network, strides 1024..1 (takeMax = upper element)
        for (int j = 1024; j >= 64; j >>= 1) {
            buf[i0] = v0; buf[i1] = v1;
            __syncthreads();
            u64 q0 = buf[i0 ^ j], q1 = buf[i1 ^ j];
            __syncthreads();
            v0 = cex(v0, q0, (i0 & j) == 0);
            v1 = cex(v1, q1, (i1 & j) == 0);
        }
        { u64 a = v0, c = v1; v0 = a > c ? a : c; v1 = a > c ? c : a; }
        for (int j = 16; j >= 1; j >>= 1) {
            u64 q0 = __shfl_xor_sync(0xffffffffu, v0, j);
            u64 q1 = __shfl_xor_sync(0xffffffffu, v1, j);
            v0 = cex(v0, q0, (i0 & j) == 0);
            v1 = cex(v1, q1, (i1 & j) == 0);
        }
    }

    // ---- publish sorted keys to smem ----
    buf[i0] = v0; buf[i1] = v1;
    __syncthreads();

    int K = min(M, K_TOP);

    // ---- extract flat indices (buf keys die after this) ----
    for (int s = tid; s < K; s += blockDim.x)
        sidx[s] = ~(unsigned int)(buf[s] & 0xffffffffull);
    __syncthreads();

    // ---- decode boxes into smem (aliases buf) ----
    float4* sbox = (float4*)buf;
    float hImg = (float)img_hw[b * 2 + 0];
    float wImg = (float)img_hw[b * 2 + 1];
    for (int s = tid; s < K; s += blockDim.x) {
        sbox[s] = decode_clip(reg, props, b, sidx[s], wImg, hImg);
        skeep[s] = 1;
    }
    __syncthreads();

    // ---- greedy NMS, serial walk + early exit at DET kept (R3 form) ----
    int kc = 0;
    for (int i = 0; i < K && kc < DET; ++i) {
        if (skeep[i]) {
            if (tid == 0) skept[kc] = i;
            float4 a = sbox[i];
            float areaA = __fmul_rn(__fsub_rn(a.z, a.x), __fsub_rn(a.w, a.y));
            for (int j = i + 1 + tid; j < K; j += blockDim.x) {
                if (skeep[j]) {
                    float4 c = sbox[j];
                    float ltx = fmaxf(a.x, c.x), lty = fmaxf(a.y, c.y);
                    float rbx = fminf(a.z, c.z), rby = fminf(a.w, c.w);
                    float w = fmaxf(__fsub_rn(rbx, ltx), 0.0f);
                    float h = fmaxf(__fsub_rn(rby, lty), 0.0f);
                    float inter = __fmul_rn(w, h);
                    if (inter > 0.0f) {
                        float areaC = __fmul_rn(__fsub_rn(c.z, c.x), __fsub_rn(c.w, c.y));
                        float uni = __fsub_rn(__fadd_rn(areaA, areaC), inter);
                        if (__fdiv_rn(inter, uni) > 0.5f) skeep[j] = 0;
                    }
                }
            }
            kc++;
            __syncthreads();
        }
    }
    __syncthreads();

    // ---- feature gather: 36 rows x 256 float4, all threads ----
    for (int idx = tid; idx < DET * (D_FEAT / 4); idx += blockDim.x) {
        int t = idx >> 8;            // detection slot
        int q = idx & 255;           // float4 within row
        float4* dst = (float4*)(out + ((size_t)b * DET + t) * D_FEAT);
        if (t < kc) {
            int pn = (int)(sidx[skept[t]] / CM1);
            const float4* src = (const float4*)(feats + ((size_t)b * N_PROP + pn) * D_FEAT);
            dst[q] = src[q];
        } else {
            dst[q] = make_float4(0.f, 0.f, 0.f, 0.f);
        }
    }

    // ---- self-reset for next graph replay ----
    if (tid == 0) g_M[b] = 0;
}

// ---------------- launch ------------------------------------------------------
extern "C" void kernel_launch(void* const* d_in, const int* in_sizes, int n_in,
                              void* d_out, int out_size) {
    const float* logits = (const float*)d_in[0];   // [8,1000,91]
    const float* reg    = (const float*)d_in[1];   // [8,1000,364]
    const float* props  = (const float*)d_in[2];   // [8,1000,4]
    const float* feats  = (const float*)d_in[3];   // [8,1000,1024]
    const int*   imghw  = (const int*)d_in[4];     // [8,2]
    float* out = (float*)d_out;                    // [8,36,1024]

    score_kernel<<<B_IMG * N_PROP / 8, 256>>>(logits, reg, props, imghw);
    fused_kernel<<<B_IMG, 1024>>>(reg, props, imghw, feats, out);
}

// round 6
// speedup vs baseline: 1.4712x; 1.0814x over previous
#include <cuda_runtime.h>
#include <math.h>

#define B_IMG 8
#define N_PROP 1000
#define C_CLS 91
#define CM1 90
#define NCAND 90000      // N_PROP * CM1
#define K_TOP 2048
#define DET 36
#define D_FEAT 1024
#define NMS_W 256        // NMS fast-path window
#define BBOX_CLIP 4.135166556742356f

typedef unsigned long long u64;

// ---------------- scratch (static device globals; zero-init at load) ---------
__device__ u64 g_list[B_IMG][NCAND];   // packed (score_bits<<32 | ~flat_idx)
__device__ int g_M[B_IMG];             // valid counts; reset by fused_kernel

// ---------------- helpers ----------------------------------------------------
__device__ __forceinline__ float4 decode_clip(const float* __restrict__ reg,
                                              const float* __restrict__ props,
                                              int b, unsigned int flat,
                                              float wImg, float hImg) {
    int n = (int)(flat / CM1);
    int c = (int)(flat % CM1) + 1;            // skip background
    const float* p = props + ((size_t)b * N_PROP + n) * 4;
    float p0 = p[0], p1 = p[1], p2 = p[2], p3 = p[3];
    float wp = __fsub_rn(p2, p0);
    float hp = __fsub_rn(p3, p1);
    float cx = __fadd_rn(p0, __fmul_rn(0.5f, wp));
    float cy = __fadd_rn(p1, __fmul_rn(0.5f, hp));
    const float* r = reg + ((size_t)b * N_PROP + n) * (C_CLS * 4) + c * 4;
    float dx = __fdiv_rn(r[0], 10.0f);
    float dy = __fdiv_rn(r[1], 10.0f);
    float dw = fminf(__fdiv_rn(r[2], 5.0f), BBOX_CLIP);
    float dh = fminf(__fdiv_rn(r[3], 5.0f), BBOX_CLIP);
    float pcx = __fadd_rn(__fmul_rn(dx, wp), cx);
    float pcy = __fadd_rn(__fmul_rn(dy, hp), cy);
    float pw  = __fmul_rn(expf(dw), wp);
    float ph  = __fmul_rn(expf(dh), hp);
    float x1 = __fsub_rn(pcx, __fmul_rn(0.5f, pw));
    float y1 = __fsub_rn(pcy, __fmul_rn(0.5f, ph));
    float x2 = __fadd_rn(pcx, __fmul_rn(0.5f, pw));
    float y2 = __fadd_rn(pcy, __fmul_rn(0.5f, ph));
    x1 = fminf(fmaxf(x1, 0.0f), wImg);
    y1 = fminf(fmaxf(y1, 0.0f), hImg);
    x2 = fminf(fmaxf(x2, 0.0f), wImg);
    y2 = fminf(fmaxf(y2, 0.0f), hImg);
    return make_float4(x1, y1, x2, y2);
}

__device__ __forceinline__ bool iou_gt_half(float4 a, float areaA, float4 c) {
    float ltx = fmaxf(a.x, c.x), lty = fmaxf(a.y, c.y);
    float rbx = fminf(a.z, c.z), rby = fminf(a.w, c.w);
    float w = fmaxf(__fsub_rn(rbx, ltx), 0.0f);
    float h = fmaxf(__fsub_rn(rby, lty), 0.0f);
    float inter = __fmul_rn(w, h);
    if (inter <= 0.0f) return false;
    float areaC = __fmul_rn(__fsub_rn(c.z, c.x), __fsub_rn(c.w, c.y));
    float uni = __fsub_rn(__fadd_rn(areaA, areaC), inter);
    return __fdiv_rn(inter, uni) > 0.5f;
}

// ---------------- kernel 1: softmax + filter + compact (warp per proposal) ---
__global__ __launch_bounds__(256)
void score_kernel(const float* __restrict__ logits,
                  const float* __restrict__ reg,
                  const float* __restrict__ props,
                  const int*   __restrict__ img_hw) {
    int warp = (blockIdx.x * blockDim.x + threadIdx.x) >> 5;   // 0..7999
    int lane = threadIdx.x & 31;
    int b = warp / N_PROP;
    int n = warp % N_PROP;

    const float* lrow = logits + (size_t)warp * C_CLS;
    float l0 = lrow[lane];
    float l1 = (lane + 32 < C_CLS) ? lrow[lane + 32] : -INFINITY;
    float l2 = (lane + 64 < C_CLS) ? lrow[lane + 64] : -INFINITY;

    float m = fmaxf(fmaxf(l0, l2), l1);
    #pragma unroll
    for (int s = 16; s > 0; s >>= 1)
        m = fmaxf(m, __shfl_xor_sync(0xffffffffu, m, s));
    m = __shfl_sync(0xffffffffu, m, 0);

    float e0 = expf(__fsub_rn(l0, m));
    float e1 = expf(__fsub_rn(l1, m));   // expf(-inf)=+0 matches zero-pad
    float e2 = expf(__fsub_rn(l2, m));

    float v = __fadd_rn(__fadd_rn(e0, e2), e1);
    #pragma unroll
    for (int s = 16; s > 0; s >>= 1)
        v = __fadd_rn(v, __shfl_xor_sync(0xffffffffu, v, s));
    float ssum = __shfl_sync(0xffffffffu, v, 0);

    float hImg = (float)img_hw[b * 2 + 0];
    float wImg = (float)img_hw[b * 2 + 1];

    float ecls[3] = {e0, e1, e2};
    #pragma unroll
    for (int k = 0; k < 3; ++k) {
        int c = lane + 32 * k;
        if (c >= 1 && c < C_CLS) {
            float score = __fdiv_rn(ecls[k], ssum);
            if (score > 0.2f) {
                unsigned int flat = (unsigned int)(n * CM1 + (c - 1));
                float4 box = decode_clip(reg, props, b, flat, wImg, hImg);
                if (__fsub_rn(box.z, box.x) >= 0.01f && __fsub_rn(box.w, box.y) >= 0.01f) {
                    int pos = atomicAdd(&g_M[b], 1);
                    u64 key = ((u64)__float_as_uint(score) << 32) |
                              (u64)(unsigned int)(~flat);
                    g_list[b][pos] = key;
                }
            }
        }
    }
}

// ---------------- register/shuffle bitonic primitives ------------------------
__device__ __forceinline__ u64 cex(u64 v, u64 p, bool takeMax) {
    return takeMax ? (v > p ? v : p) : (v < p ? v : p);
}

// Full descending bitonic sort of 2048; thread holds v0@i0, v1@i1.
__device__ __forceinline__ void sort2048(u64& v0, u64& v1, u64* buf,
                                         int i0, int i1) {
    for (int k = 2; k <= 2048; k <<= 1) {
        for (int j = k >> 1; j >= 64; j >>= 1) {
            buf[i0] = v0; buf[i1] = v1;
            __syncthreads();
            u64 p0 = buf[i0 ^ j], p1 = buf[i1 ^ j];
            __syncthreads();
            v0 = cex(v0, p0, ((i0 & j) == 0) == ((i0 & k) == 0));
            v1 = cex(v1, p1, ((i1 & j) == 0) == ((i1 & k) == 0));
        }
        if (k > 32) {   // j = 32 intra-thread
            bool desc = ((i0 & k) == 0);
            u64 a = v0, c = v1;
            v0 = desc ? (a > c ? a : c) : (a < c ? a : c);
            v1 = desc ? (a > c ? c : a) : (a < c ? c : a);
        }
        int jst = (k >> 1) < 16 ? (k >> 1) : 16;
        for (int j = jst; j >= 1; j >>= 1) {
            u64 p0 = __shfl_xor_sync(0xffffffffu, v0, j);
            u64 p1 = __shfl_xor_sync(0xffffffffu, v1, j);
            v0 = cex(v0, p0, ((i0 & j) == 0) == ((i0 & k) == 0));
            v1 = cex(v1, p1, ((i1 & j) == 0) == ((i1 & k) == 0));
        }
    }
}

// ---------------- kernel 2: fused top-K sort + window NMS + gather -----------
__global__ __launch_bounds__(1024)
void fused_kernel(const float* __restrict__ reg,
                  const float* __restrict__ props,
                  const int*   __restrict__ img_hw,
                  const float* __restrict__ feats,
                  float* __restrict__ out) {
    __shared__ u64 buf[4096];                      // 32KB; keys -> boxes (+mask alias)
    __shared__ unsigned int  sidx[K_TOP];          // 8KB
    __shared__ unsigned char skeep[K_TOP];         // 2KB (fallback only)
    __shared__ int skept[DET];
    __shared__ int s_kc;

    int b = blockIdx.x;
    int tid = threadIdx.x;
    int i0 = ((tid >> 5) << 6) + (tid & 31);
    int i1 = i0 + 32;
    int M = g_M[b];

    // ---- sort top-2048 ----
    int loaded = min(M, K_TOP);
    u64 v0 = (i0 < loaded) ? g_list[b][i0] : 0ull;
    u64 v1 = (i1 < loaded) ? g_list[b][i1] : 0ull;
    sort2048(v0, v1, buf, i0, i1);

    int consumed = loaded;
    while (consumed < M) {       // exact top-2048 merge of further chunks
        int take = min(M - consumed, K_TOP);
        u64 u0 = (i0 < take) ? g_list[b][consumed + i0] : 0ull;
        u64 u1 = (i1 < take) ? g_list[b][consumed + i1] : 0ull;
        consumed += take;
        sort2048(u0, u1, buf, i0, i1);
        buf[i0] = u0; buf[i1] = u1;
        __syncthreads();
        u64 p0 = buf[2047 - i0], p1 = buf[2047 - i1];
        __syncthreads();
        v0 = v0 > p0 ? v0 : p0;
        v1 = v1 > p1 ? v1 : p1;
        for (int j = 1024; j >= 64; j >>= 1) {
            buf[i0] = v0; buf[i1] = v1;
            __syncthreads();
            u64 q0 = buf[i0 ^ j], q1 = buf[i1 ^ j];
            __syncthreads();
            v0 = cex(v0, q0, (i0 & j) == 0);
            v1 = cex(v1, q1, (i1 & j) == 0);
        }
        { u64 a = v0, c = v1; v0 = a > c ? a : c; v1 = a > c ? c : a; }
        for (int j = 16; j >= 1; j >>= 1) {
            u64 q0 = __shfl_xor_sync(0xffffffffu, v0, j);
            u64 q1 = __shfl_xor_sync(0xffffffffu, v1, j);
            v0 = cex(v0, q0, (i0 & j) == 0);
            v1 = cex(v1, q1, (i1 & j) == 0);
        }
    }

    buf[i0] = v0; buf[i1] = v1;
    __syncthreads();

    int K = min(M, K_TOP);

    // ---- extract all flat indices (keys die after this) ----
    for (int s = tid; s < K; s += blockDim.x)
        sidx[s] = ~(unsigned int)(buf[s] & 0xffffffffull);
    __syncthreads();

    // ---- lazy decode: window boxes only ----
    float4* sbox = (float4*)buf;                         // bytes [0, 32KB)
    u64 (*smask)[4] = (u64(*)[4])(buf + 1024);           // bytes [8KB, 16KB): dead keys
    float hImg = (float)img_hw[b * 2 + 0];
    float wImg = (float)img_hw[b * 2 + 1];
    int Kw = min(K, NMS_W);
    for (int s = tid; s < Kw; s += blockDim.x)           // sbox[0..256) = bytes [0,4KB)
        sbox[s] = decode_clip(reg, props, b, sidx[s], wImg, hImg);
    __syncthreads();

    // ---- build 256x256 IoU>0.5 bitmask: thread t -> row i=t>>2, word w=t&3 ----
    {
        int i = tid >> 2, w = tid & 3;
        u64 m = 0;
        if (i < Kw) {
            float4 a = sbox[i];
            float areaA = __fmul_rn(__fsub_rn(a.z, a.x), __fsub_rn(a.w, a.y));
            int jbase = w * 64;
            int jend = min(Kw - jbase, 64);
            for (int jj = 0; jj < jend; ++jj) {
                int j = jbase + jj;
                if (j > i && iou_gt_half(a, areaA, sbox[j]))
                    m |= (1ull << jj);
            }
        }
        smask[i][w] = m;
    }
    __syncthreads();

    // ---- warp 0: greedy scan over alive bitmap (no block barriers) ----
    if (tid < 32) {
        int lane = tid;
        u64 alive = 0;
        if (lane < 4) {
            int lo = lane * 64;
            int nb = Kw - lo;
            alive = (nb <= 0) ? 0ull : (nb >= 64 ? ~0ull : ((1ull << nb) - 1ull));
        }
        int kc = 0;
        while (kc < DET) {
            unsigned int ball = __ballot_sync(0xffffffffu, alive != 0ull) & 0xFu;
            if (!ball) break;
            int fw = __ffs(ball) - 1;
            u64 word = __shfl_sync(0xffffffffu, alive, fw);
            int fb = __ffsll((long long)word) - 1;
            int i = fw * 64 + fb;
            if (lane == 0) skept[kc] = i;
            kc++;
            u64 sup = (lane < 4) ? smask[i][lane] : 0ull;
            if (lane == fw) sup |= (1ull << fb);
            alive &= ~sup;
        }
        if (lane == 0) s_kc = kc;
    }
    __syncthreads();
    int kc = s_kc;

    // ---- fallback: window exhausted with < DET kept, more candidates exist ----
    if (kc < DET && K > Kw) {
        for (int s = Kw + tid; s < K; s += blockDim.x) {
            float4 c = decode_clip(reg, props, b, sidx[s], wImg, hImg);
            sbox[s] = c;
            unsigned char kp = 1;
            for (int t = 0; t < kc; ++t) {
                float4 a = sbox[skept[t]];
                float areaA = __fmul_rn(__fsub_rn(a.z, a.x), __fsub_rn(a.w, a.y));
                if (iou_gt_half(a, areaA, c)) { kp = 0; break; }
            }
            skeep[s] = kp;
        }
        __syncthreads();
        for (int i = Kw; i < K && kc < DET; ++i) {
            if (skeep[i]) {
                if (tid == 0) skept[kc] = i;
                float4 a = sbox[i];
                float areaA = __fmul_rn(__fsub_rn(a.z, a.x), __fsub_rn(a.w, a.y));
                for (int j = i + 1 + tid; j < K; j += blockDim.x) {
                    if (skeep[j] && iou_gt_half(a, areaA, sbox[j])) skeep[j] = 0;
                }
                kc++;
                __syncthreads();
            }
        }
        __syncthreads();
    }

    // ---- feature gather: 36 rows x 256 float4 ----
    for (int idx = tid; idx < DET * (D_FEAT / 4); idx += blockDim.x) {
        int t = idx >> 8;
        int q = idx & 255;
        float4* dst = (float4*)(out + ((size_t)b * DET + t) * D_FEAT);
        if (t < kc) {
            int pn = (int)(sidx[skept[t]] / CM1);
            const float4* src = (const float4*)(feats + ((size_t)b * N_PROP + pn) * D_FEAT);
            dst[q] = src[q];
        } else {
            dst[q] = make_float4(0.f, 0.f, 0.f, 0.f);
        }
    }

    if (tid == 0) g_M[b] = 0;   // self-reset for next graph replay
}

// ---------------- launch ------------------------------------------------------
extern "C" void kernel_launch(void* const* d_in, const int* in_sizes, int n_in,
                              void* d_out, int out_size) {
    const float* logits = (const float*)d_in[0];   // [8,1000,91]
    const float* reg    = (const float*)d_in[1];   // [8,1000,364]
    const float* props  = (const float*)d_in[2];   // [8,1000,4]
    const float* feats  = (const float*)d_in[3];   // [8,1000,1024]
    const int*   imghw  = (const int*)d_in[4];     // [8,2]
    float* out = (float*)d_out;                    // [8,36,1024]

    score_kernel<<<B_IMG * N_PROP / 8, 256>>>(logits, reg, props, imghw);
    fused_kernel<<<B_IMG, 1024>>>(reg, props, imghw, feats, out);
}

// round 7
// speedup vs baseline: 1.4797x; 1.0058x over previous
#include <cuda_runtime.h>
#include <math.h>

#define B_IMG 8
#define N_PROP 1000
#define C_CLS 91
#define CM1 90
#define NCAND 90000      // N_PROP * CM1
#define K_TOP 2048
#define DET 36
#define D_FEAT 1024
#define NMS_W 256        // NMS fast-path window
#define BBOX_CLIP 4.135166556742356f

typedef unsigned long long u64;

// ---------------- scratch (static device globals; zero-init at load) ---------
__device__ u64 g_list[B_IMG][NCAND];   // packed (score_bits<<32 | ~flat_idx)
__device__ int g_M[B_IMG];             // valid counts; reset by fused_kernel

// ---------------- helpers ----------------------------------------------------
__device__ __forceinline__ float4 decode_clip(const float* __restrict__ reg,
                                              const float* __restrict__ props,
                                              int b, unsigned int flat,
                                              float wImg, float hImg) {
    int n = (int)(flat / CM1);
    int c = (int)(flat % CM1) + 1;            // skip background
    const float* p = props + ((size_t)b * N_PROP + n) * 4;
    float p0 = p[0], p1 = p[1], p2 = p[2], p3 = p[3];
    float wp = __fsub_rn(p2, p0);
    float hp = __fsub_rn(p3, p1);
    float cx = __fadd_rn(p0, __fmul_rn(0.5f, wp));
    float cy = __fadd_rn(p1, __fmul_rn(0.5f, hp));
    const float* r = reg + ((size_t)b * N_PROP + n) * (C_CLS * 4) + c * 4;
    float dx = __fdiv_rn(r[0], 10.0f);
    float dy = __fdiv_rn(r[1], 10.0f);
    float dw = fminf(__fdiv_rn(r[2], 5.0f), BBOX_CLIP);
    float dh = fminf(__fdiv_rn(r[3], 5.0f), BBOX_CLIP);
    float pcx = __fadd_rn(__fmul_rn(dx, wp), cx);
    float pcy = __fadd_rn(__fmul_rn(dy, hp), cy);
    float pw  = __fmul_rn(expf(dw), wp);
    float ph  = __fmul_rn(expf(dh), hp);
    float x1 = __fsub_rn(pcx, __fmul_rn(0.5f, pw));
    float y1 = __fsub_rn(pcy, __fmul_rn(0.5f, ph));
    float x2 = __fadd_rn(pcx, __fmul_rn(0.5f, pw));
    float y2 = __fadd_rn(pcy, __fmul_rn(0.5f, ph));
    x1 = fminf(fmaxf(x1, 0.0f), wImg);
    y1 = fminf(fmaxf(y1, 0.0f), hImg);
    x2 = fminf(fmaxf(x2, 0.0f), wImg);
    y2 = fminf(fmaxf(y2, 0.0f), hImg);
    return make_float4(x1, y1, x2, y2);
}

__device__ __forceinline__ bool iou_gt_half(float4 a, float areaA, float4 c) {
    float ltx = fmaxf(a.x, c.x), lty = fmaxf(a.y, c.y);
    float rbx = fminf(a.z, c.z), rby = fminf(a.w, c.w);
    float w = fmaxf(__fsub_rn(rbx, ltx), 0.0f);
    float h = fmaxf(__fsub_rn(rby, lty), 0.0f);
    float inter = __fmul_rn(w, h);
    if (inter <= 0.0f) return false;
    float areaC = __fmul_rn(__fsub_rn(c.z, c.x), __fsub_rn(c.w, c.y));
    float uni = __fsub_rn(__fadd_rn(areaA, areaC), inter);
    return __fdiv_rn(inter, uni) > 0.5f;
}

// ---------------- kernel 1: softmax + filter + compact (warp per proposal) ---
__global__ __launch_bounds__(256)
void score_kernel(const float* __restrict__ logits,
                  const float* __restrict__ reg,
                  const float* __restrict__ props,
                  const int*   __restrict__ img_hw) {
    int warp = (blockIdx.x * blockDim.x + threadIdx.x) >> 5;   // 0..7999
    int lane = threadIdx.x & 31;
    int b = warp / N_PROP;
    int n = warp % N_PROP;

    const float* lrow = logits + (size_t)warp * C_CLS;
    float l0 = lrow[lane];
    float l1 = (lane + 32 < C_CLS) ? lrow[lane + 32] : -INFINITY;
    float l2 = (lane + 64 < C_CLS) ? lrow[lane + 64] : -INFINITY;

    float m = fmaxf(fmaxf(l0, l2), l1);
    #pragma unroll
    for (int s = 16; s > 0; s >>= 1)
        m = fmaxf(m, __shfl_xor_sync(0xffffffffu, m, s));
    m = __shfl_sync(0xffffffffu, m, 0);

    float e0 = expf(__fsub_rn(l0, m));
    float e1 = expf(__fsub_rn(l1, m));   // expf(-inf)=+0 matches zero-pad
    float e2 = expf(__fsub_rn(l2, m));

    float v = __fadd_rn(__fadd_rn(e0, e2), e1);
    #pragma unroll
    for (int s = 16; s > 0; s >>= 1)
        v = __fadd_rn(v, __shfl_xor_sync(0xffffffffu, v, s));
    float ssum = __shfl_sync(0xffffffffu, v, 0);

    float hImg = (float)img_hw[b * 2 + 0];
    float wImg = (float)img_hw[b * 2 + 1];

    float ecls[3] = {e0, e1, e2};
    #pragma unroll
    for (int k = 0; k < 3; ++k) {
        int c = lane + 32 * k;
        if (c >= 1 && c < C_CLS) {
            float score = __fdiv_rn(ecls[k], ssum);
            if (score > 0.2f) {
                unsigned int flat = (unsigned int)(n * CM1 + (c - 1));
                float4 box = decode_clip(reg, props, b, flat, wImg, hImg);
                if (__fsub_rn(box.z, box.x) >= 0.01f && __fsub_rn(box.w, box.y) >= 0.01f) {
                    int pos = atomicAdd(&g_M[b], 1);
                    u64 key = ((u64)__float_as_uint(score) << 32) |
                              (u64)(unsigned int)(~flat);
                    g_list[b][pos] = key;
                }
            }
        }
    }
}

// ---------------- 4-key/thread register bitonic primitives -------------------
__device__ __forceinline__ u64 cex(u64 v, u64 p, bool takeMax) {
    return takeMax ? (v > p ? v : p) : (v < p ? v : p);
}
__device__ __forceinline__ void cswap(u64& a, u64& b, bool desc) {
    u64 hi = a > b ? a : b, lo = a > b ? b : a;
    a = desc ? hi : lo;
    b = desc ? lo : hi;
}

// smem compare-exchange step at stride j within phase k (k==0 => pure descending)
__device__ __forceinline__ void smem_step(u64 v[4], u64* buf, const int idx[4],
                                          int j, int k, bool active) {
    if (active) {
        #pragma unroll
        for (int r = 0; r < 4; ++r) buf[idx[r]] = v[r];
    }
    __syncthreads();
    if (active) {
        #pragma unroll
        for (int r = 0; r < 4; ++r) {
            u64 p = buf[idx[r] ^ j];
            v[r] = cex(v[r], p, ((idx[r] & j) == 0) == ((idx[r] & k) == 0));
        }
    }
    __syncthreads();
}

// in-register + shuffle tail of a phase: strides j=64,32,16..1 as applicable.
// k==0 => pure descending direction.
__device__ __forceinline__ void reg_tail(u64 v[4], const int idx[4], int lane,
                                         int k, int jstart) {
    if (jstart >= 64) {
        bool d = (k == 0) || ((idx[0] & k) == 0);
        cswap(v[0], v[2], d);
        cswap(v[1], v[3], d);
    }
    if (jstart >= 32) {
        bool d01 = (k == 0) || ((idx[0] & k) == 0);
        bool d23 = (k == 0) || ((idx[2] & k) == 0);
        cswap(v[0], v[1], d01);
        cswap(v[2], v[3], d23);
    }
    int j0 = jstart < 16 ? jstart : 16;
    for (int j = j0; j >= 1; j >>= 1) {
        #pragma unroll
        for (int r = 0; r < 4; ++r) {
            u64 p = __shfl_xor_sync(0xffffffffu, v[r], j);
            bool desc = (k == 0) || ((idx[r] & k) == 0);
            v[r] = cex(v[r], p, ((lane & j) == 0) == desc);
        }
    }
}

// full descending bitonic sort of n (power of 2, 128 <= n <= 2048);
// thread t<512 holds elements base..base+96, warps beyond n/128 idle at barriers.
__device__ void sort_n(u64 v[4], u64* buf, const int idx[4], int lane,
                       int n, bool holder) {
    for (int k = 2; k <= n; k <<= 1) {
        bool active = holder && (idx[0] < n);
        for (int j = k >> 1; j >= 128; j >>= 1)
            smem_step(v, buf, idx, j, k, active);
        if (active) reg_tail(v, idx, lane, k, k >> 1);
    }
}

// ---------------- kernel 2: fused top-K sort + window NMS + gather -----------
__global__ __launch_bounds__(1024)
void fused_kernel(const float* __restrict__ reg,
                  const float* __restrict__ props,
                  const int*   __restrict__ img_hw,
                  const float* __restrict__ feats,
                  float* __restrict__ out) {
    __shared__ u64 buf[4096];                      // 32KB; keys -> boxes (+mask alias)
    __shared__ unsigned int  sidx[K_TOP];          // 8KB
    __shared__ unsigned char skeep[K_TOP];         // 2KB (fallback only)
    __shared__ int skept[DET];
    __shared__ int s_kc;

    int b = blockIdx.x;
    int tid = threadIdx.x;
    int lane = tid & 31;
    bool holder = tid < 512;                       // 512 threads x 4 keys = 2048
    int base = ((tid >> 5) << 7) + lane;           // warp block of 128
    int idx[4] = {base, base + 32, base + 64, base + 96};
    int M = g_M[b];

    // ---- sort top chunk: runtime power-of-two size ----
    int loaded = min(M, K_TOP);
    int n = 128;
    while (n < loaded) n <<= 1;

    u64 v[4];
    #pragma unroll
    for (int r = 0; r < 4; ++r)
        v[r] = (holder && idx[r] < loaded) ? g_list[b][idx[r]] : 0ull;
    sort_n(v, buf, idx, lane, n, holder);

    // ---- exact top-2048 merge of further chunks (rare: M > 2048) ----
    int consumed = loaded;
    while (consumed < M) {
        int take = min(M - consumed, K_TOP);
        u64 u[4];
        #pragma unroll
        for (int r = 0; r < 4; ++r)
            u[r] = (holder && idx[r] < take) ? g_list[b][consumed + idx[r]] : 0ull;
        consumed += take;
        sort_n(u, buf, idx, lane, K_TOP, holder);
        // combine: v[i] = max(v[i], u[2047-i])
        if (holder) {
            #pragma unroll
            for (int r = 0; r < 4; ++r) buf[idx[r]] = u[r];
        }
        __syncthreads();
        if (holder) {
            #pragma unroll
            for (int r = 0; r < 4; ++r) {
                u64 p = buf[2047 ^ idx[r]];
                v[r] = v[r] > p ? v[r] : p;
            }
        }
        __syncthreads();
        // descending clean, strides 1024..1
        for (int j = 1024; j >= 128; j >>= 1)
            smem_step(v, buf, idx, j, 0, holder);
        if (holder) reg_tail(v, idx, lane, 0, 64);
    }

    // ---- publish sorted keys ----
    if (holder && n != 0) {
        #pragma unroll
        for (int r = 0; r < 4; ++r)
            if (idx[r] < n || M > K_TOP) buf[idx[r]] = v[r];
    }
    __syncthreads();

    int K = min(M, K_TOP);

    // ---- extract flat indices (keys die after this) ----
    for (int s = tid; s < K; s += blockDim.x)
        sidx[s] = ~(unsigned int)(buf[s] & 0xffffffffull);
    __syncthreads();

    // ---- lazy decode: window boxes only ----
    float4* sbox = (float4*)buf;                         // bytes [0, 32KB)
    u64 (*smask)[4] = (u64(*)[4])(buf + 1024);           // bytes [8KB, 16KB)
    float hImg = (float)img_hw[b * 2 + 0];
    float wImg = (float)img_hw[b * 2 + 1];
    int Kw = min(K, NMS_W);
    for (int s = tid; s < Kw; s += blockDim.x)           // sbox[0..256) = bytes [0,4KB)
        sbox[s] = decode_clip(reg, props, b, sidx[s], wImg, hImg);
    __syncthreads();

    // ---- build 256x256 IoU>0.5 bitmask: thread t -> row i=t>>2, word w=t&3 ----
    {
        int i = tid >> 2, w = tid & 3;
        u64 m = 0;
        if (i < Kw) {
            float4 a = sbox[i];
            float areaA = __fmul_rn(__fsub_rn(a.z, a.x), __fsub_rn(a.w, a.y));
            int jbase = w * 64;
            int jend = min(Kw - jbase, 64);
            for (int jj = 0; jj < jend; ++jj) {
                int j = jbase + jj;
                if (j > i && iou_gt_half(a, areaA, sbox[j]))
                    m |= (1ull << jj);
            }
        }
        smask[i][w] = m;
    }
    __syncthreads();

    // ---- warp 0: greedy scan over alive bitmap (no block barriers) ----
    if (tid < 32) {
        u64 alive = 0;
        if (lane < 4) {
            int lo = lane * 64;
            int nb = Kw - lo;
            alive = (nb <= 0) ? 0ull : (nb >= 64 ? ~0ull : ((1ull << nb) - 1ull));
        }
        int kc = 0;
        while (kc < DET) {
            unsigned int ball = __ballot_sync(0xffffffffu, alive != 0ull) & 0xFu;
            if (!ball) break;
            int fw = __ffs(ball) - 1;
            u64 word = __shfl_sync(0xffffffffu, alive, fw);
            int fb = __ffsll((long long)word) - 1;
            int i = fw * 64 + fb;
            if (lane == 0) skept[kc] = i;
            kc++;
            u64 sup = (lane < 4) ? smask[i][lane] : 0ull;
            if (lane == fw) sup |= (1ull << fb);
            alive &= ~sup;
        }
        if (lane == 0) s_kc = kc;
    }
    __syncthreads();
    int kc = s_kc;

    // ---- fallback: window exhausted with < DET kept, more candidates exist ----
    if (kc < DET && K > Kw) {
        for (int s = Kw + tid; s < K; s += blockDim.x) {
            float4 c = decode_clip(reg, props, b, sidx[s], wImg, hImg);
            sbox[s] = c;
            unsigned char kp = 1;
            for (int t = 0; t < kc; ++t) {
                float4 a = sbox[skept[t]];
                float areaA = __fmul_rn(__fsub_rn(a.z, a.x), __fsub_rn(a.w, a.y));
                if (iou_gt_half(a, areaA, c)) { kp = 0; break; }
            }
            skeep[s] = kp;
        }
        __syncthreads();
        for (int i = Kw; i < K && kc < DET; ++i) {
            if (skeep[i]) {
                if (tid == 0) skept[kc] = i;
                float4 a = sbox[i];
                float areaA = __fmul_rn(__fsub_rn(a.z, a.x), __fsub_rn(a.w, a.y));
                for (int j = i + 1 + tid; j < K; j += blockDim.x) {
                    if (skeep[j] && iou_gt_half(a, areaA, sbox[j])) skeep[j] = 0;
                }
                kc++;
                __syncthreads();
            }
        }
        __syncthreads();
    }

    // ---- feature gather: 36 rows x 256 float4 ----
    for (int idx2 = tid; idx2 < DET * (D_FEAT / 4); idx2 += blockDim.x) {
        int t = idx2 >> 8;
        int q = idx2 & 255;
        float4* dst = (float4*)(out + ((size_t)b * DET + t) * D_FEAT);
        if (t < kc) {
            int pn = (int)(sidx[skept[t]] / CM1);
            const float4* src = (const float4*)(feats + ((size_t)b * N_PROP + pn) * D_FEAT);
            dst[q] = src[q];
        } else {
            dst[q] = make_float4(0.f, 0.f, 0.f, 0.f);
        }
    }

    if (tid == 0) g_M[b] = 0;   // self-reset for next graph replay
}

// ---------------- launch ------------------------------------------------------
extern "C" void kernel_launch(void* const* d_in, const int* in_sizes, int n_in,
                              void* d_out, int out_size) {
    const float* logits = (const float*)d_in[0];   // [8,1000,91]
    const float* reg    = (const float*)d_in[1];   // [8,1000,364]
    const float* props  = (const float*)d_in[2];   // [8,1000,4]
    const float* feats  = (const float*)d_in[3];   // [8,1000,1024]
    const int*   imghw  = (const int*)d_in[4];     // [8,2]
    float* out = (float*)d_out;                    // [8,36,1024]

    score_kernel<<<B_IMG * N_PROP / 8, 256>>>(logits, reg, props, imghw);
    fused_kernel<<<B_IMG, 1024>>>(reg, props, imghw, feats, out);
}

// round 8
// speedup vs baseline: 1.6038x; 1.0839x over previous
#include <cuda_runtime.h>
#include <math.h>

#define B_IMG 8
#define N_PROP 1000
#define C_CLS 91
#define CM1 90
#define NCAND 90000
#define K_TOP 2048
#define DET 36
#define D_FEAT 1024
#define SELMAX 512
#define TARGET 256
#define CHUNK 256
#define BBOX_CLIP 4.135166556742356f

typedef unsigned long long u64;

// ---------------- scratch (static device globals; zero-init at load) ---------
__device__ u64 g_list[B_IMG][NCAND];
__device__ int g_M[B_IMG];                      // reset by select_kernel
__device__ float4 g_wbox[B_IMG][SELMAX];        // decoded boxes of top-cnt2
__device__ unsigned int g_sflat[B_IMG][SELMAX]; // flat indices of top-cnt2 (sorted)
__device__ int g_scnt[B_IMG];                   // cnt2
__device__ int g_Ktot[B_IMG];                   // min(M, 2048)
__device__ int g_Msave[B_IMG];                  // full M (for rare full path)
__device__ int g_prop[B_IMG][DET];
__device__ int g_kc[B_IMG];

// ---------------- helpers ----------------------------------------------------
__device__ __forceinline__ float4 decode_clip(const float* __restrict__ reg,
                                              const float* __restrict__ props,
                                              int b, unsigned int flat,
                                              float wImg, float hImg) {
    int n = (int)(flat / CM1);
    int c = (int)(flat % CM1) + 1;
    const float* p = props + ((size_t)b * N_PROP + n) * 4;
    float p0 = p[0], p1 = p[1], p2 = p[2], p3 = p[3];
    float wp = __fsub_rn(p2, p0);
    float hp = __fsub_rn(p3, p1);
    float cx = __fadd_rn(p0, __fmul_rn(0.5f, wp));
    float cy = __fadd_rn(p1, __fmul_rn(0.5f, hp));
    const float* r = reg + ((size_t)b * N_PROP + n) * (C_CLS * 4) + c * 4;
    float dx = __fdiv_rn(r[0], 10.0f);
    float dy = __fdiv_rn(r[1], 10.0f);
    float dw = fminf(__fdiv_rn(r[2], 5.0f), BBOX_CLIP);
    float dh = fminf(__fdiv_rn(r[3], 5.0f), BBOX_CLIP);
    float pcx = __fadd_rn(__fmul_rn(dx, wp), cx);
    float pcy = __fadd_rn(__fmul_rn(dy, hp), cy);
    float pw  = __fmul_rn(expf(dw), wp);
    float ph  = __fmul_rn(expf(dh), hp);
    float x1 = __fsub_rn(pcx, __fmul_rn(0.5f, pw));
    float y1 = __fsub_rn(pcy, __fmul_rn(0.5f, ph));
    float x2 = __fadd_rn(pcx, __fmul_rn(0.5f, pw));
    float y2 = __fadd_rn(pcy, __fmul_rn(0.5f, ph));
    x1 = fminf(fmaxf(x1, 0.0f), wImg);
    y1 = fminf(fmaxf(y1, 0.0f), hImg);
    x2 = fminf(fmaxf(x2, 0.0f), wImg);
    y2 = fminf(fmaxf(y2, 0.0f), hImg);
    return make_float4(x1, y1, x2, y2);
}

__device__ __forceinline__ bool iou_gt_half(float4 a, float areaA, float4 c) {
    float ltx = fmaxf(a.x, c.x), lty = fmaxf(a.y, c.y);
    float rbx = fminf(a.z, c.z), rby = fminf(a.w, c.w);
    float w = fmaxf(__fsub_rn(rbx, ltx), 0.0f);
    float h = fmaxf(__fsub_rn(rby, lty), 0.0f);
    float inter = __fmul_rn(w, h);
    if (inter <= 0.0f) return false;
    float areaC = __fmul_rn(__fsub_rn(c.z, c.x), __fsub_rn(c.w, c.y));
    float uni = __fsub_rn(__fadd_rn(areaA, areaC), inter);
    return __fdiv_rn(inter, uni) > 0.5f;
}

__device__ __forceinline__ int score_bin(unsigned int sb) {
    int bin = (int)(sb >> 16) - 15948;   // 0x3E4C (score 0.2) .. 0x3F80 (1.0)
    return bin < 0 ? 0 : (bin > 319 ? 319 : bin);
}

// ---------------- kernel 1: softmax + filter + compact (warp per proposal) ---
__global__ __launch_bounds__(256)
void score_kernel(const float* __restrict__ logits,
                  const float* __restrict__ reg,
                  const float* __restrict__ props,
                  const int*   __restrict__ img_hw) {
    int warp = (blockIdx.x * blockDim.x + threadIdx.x) >> 5;
    int lane = threadIdx.x & 31;
    int b = warp / N_PROP;
    int n = warp % N_PROP;

    const float* lrow = logits + (size_t)warp * C_CLS;
    float l0 = lrow[lane];
    float l1 = (lane + 32 < C_CLS) ? lrow[lane + 32] : -INFINITY;
    float l2 = (lane + 64 < C_CLS) ? lrow[lane + 64] : -INFINITY;

    float m = fmaxf(fmaxf(l0, l2), l1);
    #pragma unroll
    for (int s = 16; s > 0; s >>= 1)
        m = fmaxf(m, __shfl_xor_sync(0xffffffffu, m, s));
    m = __shfl_sync(0xffffffffu, m, 0);

    float e0 = expf(__fsub_rn(l0, m));
    float e1 = expf(__fsub_rn(l1, m));
    float e2 = expf(__fsub_rn(l2, m));

    float v = __fadd_rn(__fadd_rn(e0, e2), e1);
    #pragma unroll
    for (int s = 16; s > 0; s >>= 1)
        v = __fadd_rn(v, __shfl_xor_sync(0xffffffffu, v, s));
    float ssum = __shfl_sync(0xffffffffu, v, 0);

    float hImg = (float)img_hw[b * 2 + 0];
    float wImg = (float)img_hw[b * 2 + 1];

    float ecls[3] = {e0, e1, e2};
    #pragma unroll
    for (int k = 0; k < 3; ++k) {
        int c = lane + 32 * k;
        if (c >= 1 && c < C_CLS) {
            float score = __fdiv_rn(ecls[k], ssum);
            if (score > 0.2f) {
                unsigned int flat = (unsigned int)(n * CM1 + (c - 1));
                float4 box = decode_clip(reg, props, b, flat, wImg, hImg);
                if (__fsub_rn(box.z, box.x) >= 0.01f && __fsub_rn(box.w, box.y) >= 0.01f) {
                    int pos = atomicAdd(&g_M[b], 1);
                    u64 key = ((u64)__float_as_uint(score) << 32) |
                              (u64)(unsigned int)(~flat);
                    g_list[b][pos] = key;
                }
            }
        }
    }
}

// ---------------- 4-key/thread register bitonic primitives -------------------
__device__ __forceinline__ u64 cex(u64 v, u64 p, bool takeMax) {
    return takeMax ? (v > p ? v : p) : (v < p ? v : p);
}
__device__ __forceinline__ void cswap(u64& a, u64& b, bool desc) {
    u64 hi = a > b ? a : b, lo = a > b ? b : a;
    a = desc ? hi : lo;
    b = desc ? lo : hi;
}
__device__ __forceinline__ void smem_step(u64 v[4], u64* buf, const int idx[4],
                                          int j, int k, bool active) {
    if (active) {
        #pragma unroll
        for (int r = 0; r < 4; ++r) buf[idx[r]] = v[r];
    }
    __syncthreads();
    if (active) {
        #pragma unroll
        for (int r = 0; r < 4; ++r) {
            u64 p = buf[idx[r] ^ j];
            v[r] = cex(v[r], p, ((idx[r] & j) == 0) == ((idx[r] & k) == 0));
        }
    }
    __syncthreads();
}
__device__ __forceinline__ void reg_tail(u64 v[4], const int idx[4], int lane,
                                         int k, int jstart) {
    if (jstart >= 64) {
        bool d = (k == 0) || ((idx[0] & k) == 0);
        cswap(v[0], v[2], d);
        cswap(v[1], v[3], d);
    }
    if (jstart >= 32) {
        bool d01 = (k == 0) || ((idx[0] & k) == 0);
        bool d23 = (k == 0) || ((idx[2] & k) == 0);
        cswap(v[0], v[1], d01);
        cswap(v[2], v[3], d23);
    }
    int j0 = jstart < 16 ? jstart : 16;
    for (int j = j0; j >= 1; j >>= 1) {
        #pragma unroll
        for (int r = 0; r < 4; ++r) {
            u64 p = __shfl_xor_sync(0xffffffffu, v[r], j);
            bool desc = (k == 0) || ((idx[r] & k) == 0);
            v[r] = cex(v[r], p, ((lane & j) == 0) == desc);
        }
    }
}
__device__ void sort_n(u64 v[4], u64* buf, const int idx[4], int lane,
                       int n, bool holder) {
    for (int k = 2; k <= n; k <<= 1) {
        bool active = holder && (idx[0] < n);
        for (int j = k >> 1; j >= 128; j >>= 1)
            smem_step(v, buf, idx, j, k, active);
        if (active) reg_tail(v, idx, lane, k, k >> 1);
    }
}

// ---------------- kernel 2: histogram-threshold select + small sort ----------
__global__ __launch_bounds__(1024)
void select_kernel(const float* __restrict__ reg,
                   const float* __restrict__ props,
                   const int*   __restrict__ img_hw) {
    __shared__ int hist[320];
    __shared__ u64 selbuf[SELMAX];
    __shared__ u64 sortbuf[SELMAX];
    __shared__ int s_T, s_cnt, s_cntAb, s_pos;

    int b = blockIdx.x, tid = threadIdx.x, lane = tid & 31;
    int M = g_M[b];

    for (int i = tid; i < 320; i += 1024) hist[i] = 0;
    if (tid == 0) s_pos = 0;
    __syncthreads();
    for (int s = tid; s < M; s += 1024) {
        unsigned int sb = (unsigned int)(g_list[b][s] >> 32);
        atomicAdd(&hist[score_bin(sb)], 1);
    }
    __syncthreads();

    // threshold: warp 0, 10 bins/lane suffix scan
    if (tid < 32) {
        int lb[10]; int lsum = 0;
        #pragma unroll
        for (int r = 0; r < 10; ++r) { lb[r] = hist[lane * 10 + r]; lsum += lb[r]; }
        int suf = lsum;
        #pragma unroll
        for (int s = 1; s < 32; s <<= 1) {
            int o = __shfl_down_sync(0xffffffffu, suf, s);
            if (lane + s < 32) suf += o;
        }
        int sufN = __shfl_down_sync(0xffffffffu, suf, 1);
        if (lane == 31) sufN = 0;
        unsigned int ball = __ballot_sync(0xffffffffu, suf >= TARGET);
        if (ball == 0) {
            if (lane == 0) { s_T = 0; s_cnt = suf; s_cntAb = 0; }
        } else {
            int L = 31 - __clz(ball);
            if (lane == L) {
                int cum = sufN, T = 0, cnt = suf, cA = sufN;
                for (int r = 9; r >= 0; --r) {
                    cum += lb[r];
                    if (cum >= TARGET) { T = L * 10 + r; cnt = cum; cA = cum - lb[r]; break; }
                }
                s_T = T; s_cnt = cnt; s_cntAb = cA;
            }
        }
    }
    __syncthreads();

    bool useGT = s_cnt > SELMAX;
    int thr = s_T;
    int cnt2 = useGT ? s_cntAb : s_cnt;

    // compact selected keys (order fixed by sort below)
    for (int s = tid; s < M; s += 1024) {
        u64 key = g_list[b][s];
        int bin = score_bin((unsigned int)(key >> 32));
        bool selb = useGT ? (bin > thr) : (bin >= thr);
        if (selb) { int p = atomicAdd(&s_pos, 1); selbuf[p] = key; }
    }
    __syncthreads();

    int n = 128;
    while (n < cnt2) n <<= 1;        // n <= 512
    bool holder = tid < 512;
    int base = ((tid >> 5) << 7) + lane;
    int idx[4] = {base, base + 32, base + 64, base + 96};
    u64 v[4];
    #pragma unroll
    for (int r = 0; r < 4; ++r)
        v[r] = (holder && idx[r] < cnt2) ? selbuf[idx[r]] : 0ull;
    sort_n(v, sortbuf, idx, lane, n, holder);
    if (holder) {
        #pragma unroll
        for (int r = 0; r < 4; ++r) if (idx[r] < n) sortbuf[idx[r]] = v[r];
    }
    __syncthreads();

    float hImg = (float)img_hw[b * 2 + 0];
    float wImg = (float)img_hw[b * 2 + 1];
    for (int s = tid; s < cnt2; s += 1024) {
        unsigned int flat = ~(unsigned int)(sortbuf[s] & 0xffffffffull);
        g_sflat[b][s] = flat;
        g_wbox[b][s] = decode_clip(reg, props, b, flat, wImg, hImg);
    }
    if (tid == 0) {
        g_scnt[b] = cnt2;
        g_Ktot[b] = M < K_TOP ? M : K_TOP;
        g_Msave[b] = M;
        g_M[b] = 0;               // reset for next graph replay
    }
}

// ---------------- kernel 3: chunked NMS (+ rare exact full fallback) ---------
__global__ __launch_bounds__(1024)
void nms_kernel(const float* __restrict__ reg,
                const float* __restrict__ props,
                const int*   __restrict__ img_hw) {
    __shared__ u64 nbuf[4096];              // 32KB: swin+mask alias / full path
    __shared__ unsigned int fsidx[K_TOP];   // full path
    __shared__ unsigned char fskeep[K_TOP]; // full path
    __shared__ int skept[DET];
    __shared__ int s_kc;
    __shared__ u64 aw[4];

    int b = blockIdx.x, tid = threadIdx.x, lane = tid & 31;
    int cnt2 = g_scnt[b];
    int K = g_Ktot[b];

    float4* swin = (float4*)nbuf;               // [0, 8KB)
    u64 (*mask)[4] = (u64(*)[4])(nbuf + 1024);  // [8KB, 16KB)

    for (int s = tid; s < cnt2; s += 1024) swin[s] = g_wbox[b][s];
    if (tid == 0) s_kc = 0;
    __syncthreads();

    int kc = 0;
    for (int c0 = 0; c0 < cnt2 && kc < DET; c0 += CHUNK) {
        int c1 = min(cnt2, c0 + CHUNK);
        int csz = c1 - c0;
        if (tid < 4) {
            int lo = tid * 64, nb = csz - lo;
            aw[tid] = (nb <= 0) ? 0ull : (nb >= 64 ? ~0ull : ((1ull << nb) - 1ull));
        }
        __syncthreads();
        if (c0 > 0) {   // filter chunk against already-kept boxes
            for (int s = c0 + tid; s < c1; s += 1024) {
                float4 cbox = swin[s];
                bool al = true;
                for (int t = 0; t < kc; ++t) {
                    float4 a = swin[skept[t]];
                    float areaA = __fmul_rn(__fsub_rn(a.z, a.x), __fsub_rn(a.w, a.y));
                    if (iou_gt_half(a, areaA, cbox)) { al = false; break; }
                }
                if (!al) atomicAnd(&aw[(s - c0) >> 6], ~(1ull << ((s - c0) & 63)));
            }
        }
        __syncthreads();
        {   // intra-chunk suppression mask (upper triangle)
            int q = tid >> 2, w = tid & 3;
            u64 m = 0;
            if (q < csz) {
                float4 a = swin[c0 + q];
                float areaA = __fmul_rn(__fsub_rn(a.z, a.x), __fsub_rn(a.w, a.y));
                int jb = w * 64;
                int je = csz - jb; je = je > 64 ? 64 : je;
                for (int jj = (q + 1 > jb ? q + 1 - jb : 0); jj < je; ++jj) {
                    if (iou_gt_half(a, areaA, swin[c0 + jb + jj])) m |= (1ull << jj);
                }
            }
            mask[q][w] = m;
        }
        __syncthreads();
        if (tid < 32) {   // warp 0 greedy scan
            u64 alive = (lane < 4) ? aw[lane] : 0ull;
            int k2 = kc;
            while (k2 < DET) {
                unsigned int ball = __ballot_sync(0xffffffffu, alive != 0ull) & 0xFu;
                if (!ball) break;
                int fw = __ffs(ball) - 1;
                u64 word = __shfl_sync(0xffffffffu, alive, fw);
                int fb = __ffsll((long long)word) - 1;
                int q = fw * 64 + fb;
                if (lane == 0) skept[k2] = c0 + q;
                k2++;
                u64 sup = (lane < 4) ? mask[q][lane] : 0ull;
                if (lane == fw) sup |= (1ull << fb);
                alive &= ~sup;
            }
            if (lane == 0) s_kc = k2;
        }
        __syncthreads();
        kc = s_kc;
    }

    bool need_full = (kc < DET) && (K > cnt2);
    if (!need_full) {
        if (tid < kc) g_prop[b][tid] = (int)(g_sflat[b][skept[tid]] / CM1);
        if (tid == 0) g_kc[b] = kc;
        return;
    }

    // ---- exact full path (rare): full sort + decode + serial greedy ----
    int Mf = g_Msave[b];
    int loaded = min(Mf, K_TOP);
    int n2 = 128;
    while (n2 < loaded) n2 <<= 1;
    bool holder = tid < 512;
    int base = ((tid >> 5) << 7) + lane;
    int idx[4] = {base, base + 32, base + 64, base + 96};
    u64 v[4];
    #pragma unroll
    for (int r = 0; r < 4; ++r)
        v[r] = (holder && idx[r] < loaded) ? g_list[b][idx[r]] : 0ull;
    sort_n(v, nbuf, idx, lane, n2, holder);

    int consumed = loaded;
    while (consumed < Mf) {
        int take = min(Mf - consumed, K_TOP);
        u64 u[4];
        #pragma unroll
        for (int r = 0; r < 4; ++r)
            u[r] = (holder && idx[r] < take) ? g_list[b][consumed + idx[r]] : 0ull;
        consumed += take;
        sort_n(u, nbuf, idx, lane, K_TOP, holder);
        if (holder) {
            #pragma unroll
            for (int r = 0; r < 4; ++r) nbuf[idx[r]] = u[r];
        }
        __syncthreads();
        if (holder) {
            #pragma unroll
            for (int r = 0; r < 4; ++r) {
                u64 p = nbuf[2047 ^ idx[r]];
                v[r] = v[r] > p ? v[r] : p;
            }
        }
        __syncthreads();
        for (int j = 1024; j >= 128; j >>= 1)
            smem_step(v, nbuf, idx, j, 0, holder);
        if (holder) reg_tail(v, idx, lane, 0, 64);
    }
    if (holder) {
        #pragma unroll
        for (int r = 0; r < 4; ++r)
            if (idx[r] < n2 || Mf > K_TOP) nbuf[idx[r]] = v[r];
    }
    __syncthreads();

    for (int s = tid; s < K; s += 1024)
        fsidx[s] = ~(unsigned int)(nbuf[s] & 0xffffffffull);
    __syncthreads();

    float4* sbox = (float4*)nbuf;
    float hImg = (float)img_hw[b * 2 + 0];
    float wImg = (float)img_hw[b * 2 + 1];
    for (int s = tid; s < K; s += 1024) {
        sbox[s] = decode_clip(reg, props, b, fsidx[s], wImg, hImg);
        fskeep[s] = 1;
    }
    __syncthreads();

    kc = 0;
    for (int i = 0; i < K && kc < DET; ++i) {
        if (fskeep[i]) {
            if (tid == 0) skept[kc] = i;
            float4 a = sbox[i];
            float areaA = __fmul_rn(__fsub_rn(a.z, a.x), __fsub_rn(a.w, a.y));
            for (int j = i + 1 + tid; j < K; j += blockDim.x) {
                if (fskeep[j] && iou_gt_half(a, areaA, sbox[j])) fskeep[j] = 0;
            }
            kc++;
            __syncthreads();
        }
    }
    __syncthreads();
    if (tid < kc) g_prop[b][tid] = (int)(fsidx[skept[tid]] / CM1);
    if (tid == 0) g_kc[b] = kc;
}

// ---------------- kernel 4: wide feature gather ------------------------------
__global__ void gather_kernel(const float* __restrict__ feats,
                              float* __restrict__ out) {
    int t = blockIdx.x, b = blockIdx.y;
    int kc = g_kc[b];
    float4* dst = (float4*)(out + ((size_t)b * DET + t) * D_FEAT);
    if (t < kc) {
        const float4* src =
            (const float4*)(feats + ((size_t)b * N_PROP + g_prop[b][t]) * D_FEAT);
        dst[threadIdx.x] = src[threadIdx.x];
    } else {
        dst[threadIdx.x] = make_float4(0.f, 0.f, 0.f, 0.f);
    }
}

// ---------------- launch ------------------------------------------------------
extern "C" void kernel_launch(void* const* d_in, const int* in_sizes, int n_in,
                              void* d_out, int out_size) {
    const float* logits = (const float*)d_in[0];
    const float* reg    = (const float*)d_in[1];
    const float* props  = (const float*)d_in[2];
    const float* feats  = (const float*)d_in[3];
    const int*   imghw  = (const int*)d_in[4];
    float* out = (float*)d_out;

    score_kernel<<<B_IMG * N_PROP / 8, 256>>>(logits, reg, props, imghw);
    select_kernel<<<B_IMG, 1024>>>(reg, props, imghw);
    nms_kernel<<<B_IMG, 1024>>>(reg, props, imghw);
    gather_kernel<<<dim3(DET, B_IMG), 256>>>(feats, out);
}

// round 9
// speedup vs baseline: 1.6887x; 1.0530x over previous
#include <cuda_runtime.h>
#include <math.h>

#define B_IMG 8
#define N_PROP 1000
#define C_CLS 91
#define CM1 90
#define NCAND 90000
#define K_TOP 2048
#define DET 36
#define D_FEAT 1024
#define SELMAX 512
#define TARGET 256
#define CHUNK 256
#define BBOX_CLIP 4.135166556742356f

typedef unsigned long long u64;

// ---------------- scratch (static device globals; zero-init at load) ---------
__device__ u64 g_list[B_IMG][NCAND];
__device__ int g_M[B_IMG];              // reset by tail_kernel

// ---------------- helpers ----------------------------------------------------
__device__ __forceinline__ float4 decode_clip(const float* __restrict__ reg,
                                              const float* __restrict__ props,
                                              int b, unsigned int flat,
                                              float wImg, float hImg) {
    int n = (int)(flat / CM1);
    int c = (int)(flat % CM1) + 1;
    const float* p = props + ((size_t)b * N_PROP + n) * 4;
    float p0 = p[0], p1 = p[1], p2 = p[2], p3 = p[3];
    float wp = __fsub_rn(p2, p0);
    float hp = __fsub_rn(p3, p1);
    float cx = __fadd_rn(p0, __fmul_rn(0.5f, wp));
    float cy = __fadd_rn(p1, __fmul_rn(0.5f, hp));
    const float* r = reg + ((size_t)b * N_PROP + n) * (C_CLS * 4) + c * 4;
    float dx = __fdiv_rn(r[0], 10.0f);
    float dy = __fdiv_rn(r[1], 10.0f);
    float dw = fminf(__fdiv_rn(r[2], 5.0f), BBOX_CLIP);
    float dh = fminf(__fdiv_rn(r[3], 5.0f), BBOX_CLIP);
    float pcx = __fadd_rn(__fmul_rn(dx, wp), cx);
    float pcy = __fadd_rn(__fmul_rn(dy, hp), cy);
    float pw  = __fmul_rn(expf(dw), wp);
    float ph  = __fmul_rn(expf(dh), hp);
    float x1 = __fsub_rn(pcx, __fmul_rn(0.5f, pw));
    float y1 = __fsub_rn(pcy, __fmul_rn(0.5f, ph));
    float x2 = __fadd_rn(pcx, __fmul_rn(0.5f, pw));
    float y2 = __fadd_rn(pcy, __fmul_rn(0.5f, ph));
    x1 = fminf(fmaxf(x1, 0.0f), wImg);
    y1 = fminf(fmaxf(y1, 0.0f), hImg);
    x2 = fminf(fmaxf(x2, 0.0f), wImg);
    y2 = fminf(fmaxf(y2, 0.0f), hImg);
    return make_float4(x1, y1, x2, y2);
}

__device__ __forceinline__ bool iou_gt_half(float4 a, float areaA, float4 c) {
    float ltx = fmaxf(a.x, c.x), lty = fmaxf(a.y, c.y);
    float rbx = fminf(a.z, c.z), rby = fminf(a.w, c.w);
    float w = fmaxf(__fsub_rn(rbx, ltx), 0.0f);
    float h = fmaxf(__fsub_rn(rby, lty), 0.0f);
    float inter = __fmul_rn(w, h);
    if (inter <= 0.0f) return false;
    float areaC = __fmul_rn(__fsub_rn(c.z, c.x), __fsub_rn(c.w, c.y));
    float uni = __fsub_rn(__fadd_rn(areaA, areaC), inter);
    return __fdiv_rn(inter, uni) > 0.5f;
}

__device__ __forceinline__ int score_bin(unsigned int sb) {
    int bin = (int)(sb >> 16) - 15948;   // 0x3E4C (0.2) .. 0x3F80 (1.0)
    return bin < 0 ? 0 : (bin > 319 ? 319 : bin);
}

// ---------------- kernel 1: softmax + filter + compact (warp per proposal) ---
__global__ __launch_bounds__(256)
void score_kernel(const float* __restrict__ logits,
                  const float* __restrict__ reg,
                  const float* __restrict__ props,
                  const int*   __restrict__ img_hw) {
    int warp = (blockIdx.x * blockDim.x + threadIdx.x) >> 5;
    int lane = threadIdx.x & 31;
    int b = warp / N_PROP;
    int n = warp % N_PROP;

    const float* lrow = logits + (size_t)warp * C_CLS;
    float l0 = lrow[lane];
    float l1 = (lane + 32 < C_CLS) ? lrow[lane + 32] : -INFINITY;
    float l2 = (lane + 64 < C_CLS) ? lrow[lane + 64] : -INFINITY;

    float m = fmaxf(fmaxf(l0, l2), l1);
    #pragma unroll
    for (int s = 16; s > 0; s >>= 1)
        m = fmaxf(m, __shfl_xor_sync(0xffffffffu, m, s));
    m = __shfl_sync(0xffffffffu, m, 0);

    float e0 = expf(__fsub_rn(l0, m));
    float e1 = expf(__fsub_rn(l1, m));
    float e2 = expf(__fsub_rn(l2, m));

    float v = __fadd_rn(__fadd_rn(e0, e2), e1);
    #pragma unroll
    for (int s = 16; s > 0; s >>= 1)
        v = __fadd_rn(v, __shfl_xor_sync(0xffffffffu, v, s));
    float ssum = __shfl_sync(0xffffffffu, v, 0);

    float hImg = (float)img_hw[b * 2 + 0];
    float wImg = (float)img_hw[b * 2 + 1];

    float ecls[3] = {e0, e1, e2};
    #pragma unroll
    for (int k = 0; k < 3; ++k) {
        int c = lane + 32 * k;
        if (c >= 1 && c < C_CLS) {
            float score = __fdiv_rn(ecls[k], ssum);
            if (score > 0.2f) {
                unsigned int flat = (unsigned int)(n * CM1 + (c - 1));
                float4 box = decode_clip(reg, props, b, flat, wImg, hImg);
                if (__fsub_rn(box.z, box.x) >= 0.01f && __fsub_rn(box.w, box.y) >= 0.01f) {
                    int pos = atomicAdd(&g_M[b], 1);
                    u64 key = ((u64)__float_as_uint(score) << 32) |
                              (u64)(unsigned int)(~flat);
                    g_list[b][pos] = key;
                }
            }
        }
    }
}

// ---------------- 4-key/thread register bitonic primitives -------------------
__device__ __forceinline__ u64 cex(u64 v, u64 p, bool takeMax) {
    return takeMax ? (v > p ? v : p) : (v < p ? v : p);
}
__device__ __forceinline__ void cswap(u64& a, u64& b, bool desc) {
    u64 hi = a > b ? a : b, lo = a > b ? b : a;
    a = desc ? hi : lo;
    b = desc ? lo : hi;
}
__device__ __forceinline__ void smem_step(u64 v[4], u64* buf, const int idx[4],
                                          int j, int k, bool active) {
    if (active) {
        #pragma unroll
        for (int r = 0; r < 4; ++r) buf[idx[r]] = v[r];
    }
    __syncthreads();
    if (active) {
        #pragma unroll
        for (int r = 0; r < 4; ++r) {
            u64 p = buf[idx[r] ^ j];
            v[r] = cex(v[r], p, ((idx[r] & j) == 0) == ((idx[r] & k) == 0));
        }
    }
    __syncthreads();
}
__device__ __forceinline__ void reg_tail(u64 v[4], const int idx[4], int lane,
                                         int k, int jstart) {
    if (jstart >= 64) {
        bool d = (k == 0) || ((idx[0] & k) == 0);
        cswap(v[0], v[2], d);
        cswap(v[1], v[3], d);
    }
    if (jstart >= 32) {
        bool d01 = (k == 0) || ((idx[0] & k) == 0);
        bool d23 = (k == 0) || ((idx[2] & k) == 0);
        cswap(v[0], v[1], d01);
        cswap(v[2], v[3], d23);
    }
    int j0 = jstart < 16 ? jstart : 16;
    for (int j = j0; j >= 1; j >>= 1) {
        #pragma unroll
        for (int r = 0; r < 4; ++r) {
            u64 p = __shfl_xor_sync(0xffffffffu, v[r], j);
            bool desc = (k == 0) || ((idx[r] & k) == 0);
            v[r] = cex(v[r], p, ((lane & j) == 0) == desc);
        }
    }
}
__device__ void sort_n(u64 v[4], u64* buf, const int idx[4], int lane,
                       int n, bool holder) {
    for (int k = 2; k <= n; k <<= 1) {
        bool active = holder && (idx[0] < n);
        for (int j = k >> 1; j >= 128; j >>= 1)
            smem_step(v, buf, idx, j, k, active);
        if (active) reg_tail(v, idx, lane, k, k >> 1);
    }
}

// ---------------- kernel 2: fused select + NMS + gather (1 block / image) ----
__global__ __launch_bounds__(1024)
void tail_kernel(const float* __restrict__ reg,
                 const float* __restrict__ props,
                 const int*   __restrict__ img_hw,
                 const float* __restrict__ feats,
                 float* __restrict__ out) {
    __shared__ u64 nbuf[4096];               // 32KB multi-purpose
    __shared__ unsigned int fsidx[K_TOP];    // 8KB (full path)
    __shared__ unsigned char fskeep[K_TOP];  // 2KB (full path)
    __shared__ unsigned int sflat[SELMAX];   // 2KB
    __shared__ int skept[DET];
    __shared__ int pprop[DET];
    __shared__ int s_kc, s_T, s_cnt, s_cntAb, s_pos;
    __shared__ u64 aw[4];

    int* hist      = (int*)nbuf;             // 320 ints, dead after threshold
    u64* selbuf    = nbuf + 512;             // 512 keys, dead after sort load
    u64* sortbuf   = nbuf + 1024;            // 512 keys (sorted)
    float4* wbox   = (float4*)nbuf;          // 512 boxes = nbuf[0..1024)
    u64 (*mask)[4] = (u64(*)[4])(nbuf + 1536);

    int b = blockIdx.x, tid = threadIdx.x, lane = tid & 31;
    int M = g_M[b];

    // ---- phase 1: histogram over score bins ----
    for (int i = tid; i < 320; i += 1024) hist[i] = 0;
    if (tid == 0) s_pos = 0;
    __syncthreads();
    for (int s = tid; s < M; s += 1024) {
        unsigned int sb = (unsigned int)(g_list[b][s] >> 32);
        atomicAdd(&hist[score_bin(sb)], 1);
    }
    __syncthreads();

    // ---- phase 2: threshold (warp 0, 10 bins/lane suffix scan) ----
    if (tid < 32) {
        int lb[10]; int lsum = 0;
        #pragma unroll
        for (int r = 0; r < 10; ++r) { lb[r] = hist[lane * 10 + r]; lsum += lb[r]; }
        int suf = lsum;
        #pragma unroll
        for (int s = 1; s < 32; s <<= 1) {
            int o = __shfl_down_sync(0xffffffffu, suf, s);
            if (lane + s < 32) suf += o;
        }
        int sufN = __shfl_down_sync(0xffffffffu, suf, 1);
        if (lane == 31) sufN = 0;
        unsigned int ball = __ballot_sync(0xffffffffu, suf >= TARGET);
        if (ball == 0) {
            if (lane == 0) { s_T = 0; s_cnt = suf; s_cntAb = 0; }
        } else {
            int L = 31 - __clz(ball);
            if (lane == L) {
                int cum = sufN, T = 0, cnt = suf, cA = sufN;
                for (int r = 9; r >= 0; --r) {
                    cum += lb[r];
                    if (cum >= TARGET) { T = L * 10 + r; cnt = cum; cA = cum - lb[r]; break; }
                }
                s_T = T; s_cnt = cnt; s_cntAb = cA;
            }
        }
    }
    __syncthreads();

    bool useGT = s_cnt > SELMAX;
    int thr = s_T;
    int cnt2 = useGT ? s_cntAb : s_cnt;

    // ---- phase 3: compact selected keys ----
    for (int s = tid; s < M; s += 1024) {
        u64 key = g_list[b][s];
        int bin = score_bin((unsigned int)(key >> 32));
        bool selb = useGT ? (bin > thr) : (bin >= thr);
        if (selb) { int p = atomicAdd(&s_pos, 1); selbuf[p] = key; }
    }
    __syncthreads();

    // ---- phase 4: sort <=512 keys ----
    int n = 128;
    while (n < cnt2) n <<= 1;
    bool holder = tid < 512;
    int base = ((tid >> 5) << 7) + lane;
    int idx[4] = {base, base + 32, base + 64, base + 96};
    u64 v[4];
    #pragma unroll
    for (int r = 0; r < 4; ++r)
        v[r] = (holder && idx[r] < cnt2) ? selbuf[idx[r]] : 0ull;
    __syncthreads();            // selbuf fully read before wbox aliases it later
    sort_n(v, sortbuf, idx, lane, n, holder);
    if (holder) {
        #pragma unroll
        for (int r = 0; r < 4; ++r) if (idx[r] < n) sortbuf[idx[r]] = v[r];
    }
    __syncthreads();

    // ---- phase 5: decode window boxes into smem ----
    float hImg = (float)img_hw[b * 2 + 0];
    float wImg = (float)img_hw[b * 2 + 1];
    for (int s = tid; s < cnt2; s += 1024) {
        unsigned int flat = ~(unsigned int)(sortbuf[s] & 0xffffffffull);
        sflat[s] = flat;
        wbox[s] = decode_clip(reg, props, b, flat, wImg, hImg);
    }
    if (tid == 0) s_kc = 0;
    __syncthreads();

    // ---- phase 6: chunked NMS ----
    int kc = 0;
    for (int c0 = 0; c0 < cnt2 && kc < DET; c0 += CHUNK) {
        int c1 = min(cnt2, c0 + CHUNK);
        int csz = c1 - c0;
        if (tid < 4) {
            int lo = tid * 64, nb = csz - lo;
            aw[tid] = (nb <= 0) ? 0ull : (nb >= 64 ? ~0ull : ((1ull << nb) - 1ull));
        }
        __syncthreads();
        if (c0 > 0) {
            for (int s = c0 + tid; s < c1; s += 1024) {
                float4 cbox = wbox[s];
                bool al = true;
                for (int t = 0; t < kc; ++t) {
                    float4 a = wbox[skept[t]];
                    float areaA = __fmul_rn(__fsub_rn(a.z, a.x), __fsub_rn(a.w, a.y));
                    if (iou_gt_half(a, areaA, cbox)) { al = false; break; }
                }
                if (!al) atomicAnd(&aw[(s - c0) >> 6], ~(1ull << ((s - c0) & 63)));
            }
        }
        __syncthreads();
        {
            int q = tid >> 2, w = tid & 3;
            u64 m = 0;
            if (q < csz) {
                float4 a = wbox[c0 + q];
                float areaA = __fmul_rn(__fsub_rn(a.z, a.x), __fsub_rn(a.w, a.y));
                int jb = w * 64;
                int je = csz - jb; je = je > 64 ? 64 : je;
                for (int jj = (q + 1 > jb ? q + 1 - jb : 0); jj < je; ++jj) {
                    if (iou_gt_half(a, areaA, wbox[c0 + jb + jj])) m |= (1ull << jj);
                }
            }
            mask[q][w] = m;
        }
        __syncthreads();
        if (tid < 32) {
            u64 alive = (lane < 4) ? aw[lane] : 0ull;
            int k2 = kc;
            while (k2 < DET) {
                unsigned int ball = __ballot_sync(0xffffffffu, alive != 0ull) & 0xFu;
                if (!ball) break;
                int fw = __ffs(ball) - 1;
                u64 word = __shfl_sync(0xffffffffu, alive, fw);
                int fb = __ffsll((long long)word) - 1;
                int q = fw * 64 + fb;
                if (lane == 0) skept[k2] = c0 + q;
                k2++;
                u64 sup = (lane < 4) ? mask[q][lane] : 0ull;
                if (lane == fw) sup |= (1ull << fb);
                alive &= ~sup;
            }
            if (lane == 0) s_kc = k2;
        }
        __syncthreads();
        kc = s_kc;
    }

    int K = M < K_TOP ? M : K_TOP;
    bool need_full = (kc < DET) && (K > cnt2);

    if (!need_full) {
        if (tid < kc) pprop[tid] = (int)(sflat[skept[tid]] / CM1);
    } else {
        // ---- exact full path (rare): full sort + decode + serial greedy ----
        int loaded = K;
        int n2 = 128;
        while (n2 < loaded) n2 <<= 1;
        u64 w[4];
        #pragma unroll
        for (int r = 0; r < 4; ++r)
            w[r] = (holder && idx[r] < loaded) ? g_list[b][idx[r]] : 0ull;
        __syncthreads();
        sort_n(w, nbuf, idx, lane, n2, holder);

        int consumed = loaded;
        while (consumed < M) {
            int take = min(M - consumed, K_TOP);
            u64 u[4];
            #pragma unroll
            for (int r = 0; r < 4; ++r)
                u[r] = (holder && idx[r] < take) ? g_list[b][consumed + idx[r]] : 0ull;
            consumed += take;
            sort_n(u, nbuf, idx, lane, K_TOP, holder);
            if (holder) {
                #pragma unroll
                for (int r = 0; r < 4; ++r) nbuf[idx[r]] = u[r];
            }
            __syncthreads();
            if (holder) {
                #pragma unroll
                for (int r = 0; r < 4; ++r) {
                    u64 p = nbuf[2047 ^ idx[r]];
                    w[r] = w[r] > p ? w[r] : p;
                }
            }
            __syncthreads();
            for (int j = 1024; j >= 128; j >>= 1)
                smem_step(w, nbuf, idx, j, 0, holder);
            if (holder) reg_tail(w, idx, lane, 0, 64);
        }
        if (holder) {
            #pragma unroll
            for (int r = 0; r < 4; ++r)
                if (idx[r] < n2 || M > K_TOP) nbuf[idx[r]] = w[r];
        }
        __syncthreads();

        for (int s = tid; s < K; s += 1024)
            fsidx[s] = ~(unsigned int)(nbuf[s] & 0xffffffffull);
        __syncthreads();

        float4* sbox = (float4*)nbuf;
        for (int s = tid; s < K; s += 1024) {
            sbox[s] = decode_clip(reg, props, b, fsidx[s], wImg, hImg);
            fskeep[s] = 1;
        }
        __syncthreads();

        kc = 0;
        for (int i = 0; i < K && kc < DET; ++i) {
            if (fskeep[i]) {
                if (tid == 0) skept[kc] = i;
                float4 a = sbox[i];
                float areaA = __fmul_rn(__fsub_rn(a.z, a.x), __fsub_rn(a.w, a.y));
                for (int j = i + 1 + tid; j < K; j += blockDim.x) {
                    if (fskeep[j] && iou_gt_half(a, areaA, sbox[j])) fskeep[j] = 0;
                }
                kc++;
                __syncthreads();
            }
        }
        __syncthreads();
        if (tid < kc) pprop[tid] = (int)(fsidx[skept[tid]] / CM1);
    }
    __syncthreads();

    // ---- phase 7: feature gather (36 rows x 256 float4) ----
    for (int id = tid; id < DET * (D_FEAT / 4); id += 1024) {
        int t = id >> 8, q = id & 255;
        float4* dst = (float4*)(out + ((size_t)b * DET + t) * D_FEAT);
        if (t < kc) {
            const float4* src =
                (const float4*)(feats + ((size_t)b * N_PROP + pprop[t]) * D_FEAT);
            dst[q] = src[q];
        } else {
            dst[q] = make_float4(0.f, 0.f, 0.f, 0.f);
        }
    }

    if (tid == 0) g_M[b] = 0;   // reset for next graph replay
}

// ---------------- launch ------------------------------------------------------
extern "C" void kernel_launch(void* const* d_in, const int* in_sizes, int n_in,
                              void* d_out, int out_size) {
    const float* logits = (const float*)d_in[0];
    const float* reg    = (const float*)d_in[1];
    const float* props  = (const float*)d_in[2];
    const float* feats  = (const float*)d_in[3];
    const int*   imghw  = (const int*)d_in[4];
    float* out = (float*)d_out;

    score_kernel<<<B_IMG * N_PROP / 8, 256>>>(logits, reg, props, imghw);
    tail_kernel<<<B_IMG, 1024>>>(reg, props, imghw, feats, out);
}